// round 16
// baseline (speedup 1.0000x reference)
#include <cuda_runtime.h>
#include <stdint.h>

// ---------------- problem constants ----------------
#define NB     16
#define NPROP  2000
#define NGT    100
#define NGTP   104      // padded to 8*13
#define NPOS   66
#define NNEG   134
#define NROI   200
#define HH     160
#define WW     160
#define MH     28
#define MW     28

// output layout (float32, concatenated flattened tuple)
#define ROIS_OFF 0
#define CLS_OFF  (NB*NROI*4)                 // 12800
#define DEL_OFF  (CLS_OFF + NB*NROI)         // 16000
#define MSK_OFF  (DEL_OFF + NB*NROI*4)       // 28800

// ---------------- scratch (__device__ globals; no allocs allowed) ----------------
__device__ unsigned char g_flags [NB*NPROP];  // bit0: iou_max>=0.5, bit1: proposal valid
__device__ int           g_ioarg [NB*NPROP];
__device__ float         g_posbox[NB*NPOS*4];
__device__ int           g_posgt [NB*NPOS];   // gt index, -1 if slot invalid

// ---------------- JAX threefry2x32 (partitionable-default semantics) ----------------
__device__ __forceinline__ void tf2x32(uint32_t k0, uint32_t k1,
                                       uint32_t x0, uint32_t x1,
                                       uint32_t &o0, uint32_t &o1) {
    uint32_t ks2 = k0 ^ k1 ^ 0x1BD11BDAu;
    x0 += k0; x1 += k1;
#define TF_RND(r) { x0 += x1; x1 = __funnelshift_l(x1, x1, (r)); x1 ^= x0; }
    TF_RND(13) TF_RND(15) TF_RND(26) TF_RND(6)
    x0 += k1;  x1 += ks2 + 1u;
    TF_RND(17) TF_RND(29) TF_RND(16) TF_RND(24)
    x0 += ks2; x1 += k0 + 2u;
    TF_RND(13) TF_RND(15) TF_RND(26) TF_RND(6)
    x0 += k0;  x1 += k1 + 3u;
    TF_RND(17) TF_RND(29) TF_RND(16) TF_RND(24)
    x0 += k1;  x1 += ks2 + 4u;
    TF_RND(13) TF_RND(15) TF_RND(26) TF_RND(6)
    x0 += ks2; x1 += k0 + 5u;
#undef TF_RND
    o0 = x0; o1 = x1;
}

__device__ __forceinline__ float jax_uniform(uint32_t k0, uint32_t k1, uint32_t i) {
    uint32_t a, b;
    tf2x32(k0, k1, 0u, i, a, b);
    uint32_t bits = a ^ b;
    return __uint_as_float((bits >> 9) | 0x3f800000u) - 1.0f;
}

// ---------------- Kernel 0: per-proposal IoU max / argmax ----------------
// 8 lanes per proposal (13 GTs each, padded). Division-free rational tracking
// with safe-margin cross-multiply compare; rare exact-division fallback keeps
// the selection bit-identical to argmax over rounded quotients.
__global__ __launch_bounds__(256) void k_iou(const float* __restrict__ prop,
                                             const int*   __restrict__ gcls,
                                             const float* __restrict__ gbox) {
    __shared__ float4 sg4[NGTP];
    __shared__ float  sa [NGTP];   // gt area, NaN if class invalid / padding
    int b = blockIdx.y, tid = threadIdx.x;
    for (int t = tid; t < NGTP; t += 256) {
        if (t < NGT) {
            float4 g = *reinterpret_cast<const float4*>(gbox + (size_t)(b*NGT + t)*4);
            sg4[t] = g;
            float a2 = (g.z - g.x) * (g.w - g.y);
            sa[t] = (gcls[b*NGT + t] > 0) ? a2 : __int_as_float(0x7FC00000);
        } else {
            sg4[t] = make_float4(0.f, 0.f, 0.f, 0.f);
            sa[t]  = __int_as_float(0x7FC00000);
        }
    }
    __syncthreads();

    int gi = blockIdx.x * 32 + (tid >> 3);   // proposal index within image
    int r  = tid & 7;                        // gt-eighth
    if (gi >= NPROP) return;

    const float4 p = *reinterpret_cast<const float4*>(prop + (size_t)(b*NPROP + gi)*4);
    float a1 = (p.z - p.x) * (p.w - p.y);

    float ib = -1.0f, ub = 1.0f;             // best as rational: q = ib/ub
    int   arg = r * 13;
    const float UP = 1.0f + 2e-6f, DN = 1.0f - 2e-6f;

    #pragma unroll
    for (int k = 0; k < 13; k++) {
        int g = r * 13 + k;
        float4 gb = sg4[g];
        float a2 = sa[g];
        float yA = fmaxf(p.x, gb.x), xA = fmaxf(p.y, gb.y);
        float yB = fminf(p.z, gb.z), xB = fminf(p.w, gb.w);
        float inter = fmaxf(yB - yA, 0.f) * fmaxf(xB - xA, 0.f);
        float uni = fmaxf(a1 + a2 - inter, 1e-10f);
        bool gok = (a2 == a2);               // false for NaN (invalid/pad)
        if (inter == 0.0f) {
            if (gok && ib < 0.0f) { ib = 0.0f; ub = uni; arg = g; }
        } else if (gok) {
            float c1 = __fmul_rn(inter, ub);
            float c2 = __fmul_rn(ib, uni);
            if (c1 > __fmul_rn(c2, UP)) {            // provably RN(qn) > RN(qb)
                ib = inter; ub = uni; arg = g;
            } else if (c1 >= __fmul_rn(c2, DN)) {    // ambiguous band: exact check
                float qn = __fdiv_rn(inter, uni);
                float qb = __fdiv_rn(ib, ub);
                if (qn > qb) { ib = inter; ub = uni; arg = g; }
            }
        }
    }

    // merge 8 segments: max rounded value, tie -> min gt index (argmax-first)
    #pragma unroll
    for (int off = 4; off >= 1; off >>= 1) {
        float i2 = __shfl_down_sync(0xFFFFFFFFu, ib,  off, 8);
        float u2 = __shfl_down_sync(0xFFFFFFFFu, ub,  off, 8);
        int   a2 = __shfl_down_sync(0xFFFFFFFFu, arg, off, 8);
        bool rep;
        if (ib < 0.0f)       rep = (i2 >= 0.0f);      // anything beats sentinel
        else if (i2 < 0.0f)  rep = false;
        else {
            float c1 = __fmul_rn(i2, ub);
            float c2 = __fmul_rn(ib, u2);
            if (c1 > __fmul_rn(c2, UP))      rep = true;
            else if (c1 < __fmul_rn(c2, DN)) rep = false;
            else {
                float qn = __fdiv_rn(i2, u2);
                float qb = __fdiv_rn(ib, ub);
                rep = (qn > qb) || (qn == qb && a2 < arg);
            }
        }
        if (rep) { ib = i2; ub = u2; arg = a2; }
    }
    if (r == 0) {
        float q = __fdiv_rn(ib, ub);         // exact rounded max (one div/proposal)
        bool valid = (p.x != 0.f) || (p.y != 0.f) || (p.z != 0.f) || (p.w != 0.f);
        g_flags[b*NPROP + gi] = (unsigned char)((q >= 0.5f ? 1 : 0) | (valid ? 2 : 0));
        g_ioarg[b*NPROP + gi] = arg;
    }
}

// ---------------- helpers for register bitonic ----------------
typedef unsigned long long ull;
__device__ __forceinline__ void cmpex(ull &A, ull &B, bool desc) {
    if ((A < B) == desc) { ull t = A; A = B; B = t; }
}
__device__ __forceinline__ uint32_t fmap(float f) {
    uint32_t u = __float_as_uint(f);
    return (u >> 31) ? ~u : (u | 0x80000000u);
}

// ---------------- Kernel 1: sampling. grid = (image, role[pos|neg]) ----------------
// Bitonic sort of 2048 64-bit keys, DESCENDING: key = (fmap(score)<<32) |
// (0xFFFFFFFF - idx) gives descending score, ascending-index ties (lax.top_k).
// 4 elements/thread: j<=2 in registers, j=4..64 via shfl, j>=128 via smem.
__global__ __launch_bounds__(512) void k_sample(const float* __restrict__ prop,
                                                const int*   __restrict__ gcls,
                                                const float* __restrict__ gbox,
                                                const float* __restrict__ stddev,
                                                float*       __restrict__ out) {
    __shared__ ull sk[2048];
    __shared__ int scnt;
    int b = blockIdx.x, role = blockIdx.y, tid = threadIdx.x;

    uint32_t kb0, kb1, kp0, kp1, kn0, kn1;
    tf2x32(0u, 42u, 0u, (uint32_t)b, kb0, kb1);
    tf2x32(kb0, kb1, 0u, 0u, kp0, kp1);
    tf2x32(kb0, kb1, 0u, 1u, kn0, kn1);
    uint32_t sk0 = role ? kn0 : kp0, sk1 = role ? kn1 : kp1;

    if (tid == 0) scnt = 0;
    __syncthreads();

    ull reg[4];
    int cnt = 0;
    #pragma unroll
    for (int s = 0; s < 4; s++) {
        int i = tid * 4 + s;
        uint32_t key32 = 0;                       // filler sorts last
        if (i < NPROP) {
            unsigned char f = g_flags[b*NPROP + i];
            bool posc = (f & 3) == 3;             // iou>=0.5 && valid
            bool cand = role ? ((f & 2) && !(f & 1)) : posc;
            float sc = cand ? jax_uniform(sk0, sk1, (uint32_t)i) : -1.0f;
            key32 = fmap(sc);
            if (role && posc && jax_uniform(kp0, kp1, (uint32_t)i) > 0.0f) cnt++;
        }
        reg[s] = ((ull)key32 << 32) | (uint32_t)(0xFFFFFFFFu - (uint32_t)i);
    }
    if (role && cnt) atomicAdd(&scnt, cnt);

    for (int k = 2; k <= 2048; k <<= 1) {
        for (int j = k >> 1; j > 0; j >>= 1) {
            if (j >= 128) {
                __syncthreads();
                #pragma unroll
                for (int s = 0; s < 4; s++) sk[tid*4 + s] = reg[s];
                __syncthreads();
                #pragma unroll
                for (int s = 0; s < 4; s++) {
                    int e = tid*4 + s;
                    ull part = sk[e ^ j];
                    bool desc = ((e & k) == 0), lower = ((e & j) == 0);
                    bool takeMax = (desc == lower);
                    ull A = reg[s];
                    reg[s] = takeMax ? (A > part ? A : part) : (A < part ? A : part);
                }
            } else if (j >= 4) {
                int lx = j >> 2;
                bool lower = ((tid & lx) == 0);
                #pragma unroll
                for (int s = 0; s < 4; s++) {
                    ull part = __shfl_xor_sync(0xFFFFFFFFu, reg[s], lx);
                    int e = tid*4 + s;
                    bool desc = ((e & k) == 0);
                    bool takeMax = (desc == lower);
                    ull A = reg[s];
                    reg[s] = takeMax ? (A > part ? A : part) : (A < part ? A : part);
                }
            } else if (j == 2) {                   // k >= 4 here: desc uniform in s
                bool desc = (((tid*4) & k) == 0);
                cmpex(reg[0], reg[2], desc);
                cmpex(reg[1], reg[3], desc);
            } else {                               // j == 1
                if (k == 2) { cmpex(reg[0], reg[1], true); cmpex(reg[2], reg[3], false); }
                else {
                    bool desc = (((tid*4) & k) == 0);
                    cmpex(reg[0], reg[1], desc);
                    cmpex(reg[2], reg[3], desc);
                }
            }
        }
    }
    __syncthreads();
    #pragma unroll
    for (int s = 0; s < 4; s++) sk[tid*4 + s] = reg[s];
    __syncthreads();

    if (role == 0) {
        // ---- positives: slots [0,66) ----
        if (tid < NPOS) {
            int t = tid;
            ull key = sk[t];
            bool valid = (uint32_t)(key >> 32) > 0x80000000u;   // score > 0
            int  idx   = (int)(0xFFFFFFFFu - (uint32_t)key);
            const float4 p = *reinterpret_cast<const float4*>(prop + (size_t)(b*NPROP + idx)*4);
            int g = g_ioarg[b*NPROP + idx];

            float* rr = out + ROIS_OFF + (size_t)(b*NROI + t)*4;
            rr[0] = valid ? p.x : 0.f; rr[1] = valid ? p.y : 0.f;
            rr[2] = valid ? p.z : 0.f; rr[3] = valid ? p.w : 0.f;

            float d0 = 0.f, d1 = 0.f, d2 = 0.f, d3 = 0.f;
            int cls = 0;
            if (valid) {
                const float4 gb = *reinterpret_cast<const float4*>(gbox + (size_t)(b*NGT + g)*4);
                cls = gcls[b*NGT + g];
                float h  = p.z - p.x,  w  = p.w - p.y;
                float cy = p.x + 0.5f*h, cx = p.y + 0.5f*w;
                float gh = gb.z - gb.x, gw = gb.w - gb.y;
                float gcy = gb.x + 0.5f*gh, gcx = gb.y + 0.5f*gw;
                d0 = __fdiv_rn(__fdiv_rn(gcy - cy, h), stddev[0]);
                d1 = __fdiv_rn(__fdiv_rn(gcx - cx, w), stddev[1]);
                d2 = __fdiv_rn(logf(__fdiv_rn(gh, h)), stddev[2]);
                d3 = __fdiv_rn(logf(__fdiv_rn(gw, w)), stddev[3]);
            }
            out[CLS_OFF + b*NROI + t] = (float)cls;
            float* d = out + DEL_OFF + (size_t)(b*NROI + t)*4;
            d[0] = d0; d[1] = d1; d[2] = d2; d[3] = d3;

            g_posbox[(b*NPOS + t)*4 + 0] = p.x;
            g_posbox[(b*NPOS + t)*4 + 1] = p.y;
            g_posbox[(b*NPOS + t)*4 + 2] = p.z;
            g_posbox[(b*NPOS + t)*4 + 3] = p.w;
            g_posgt[b*NPOS + t] = valid ? g : -1;
        }
    } else {
        // ---- negatives: slots [66,200) ----
        int P = min(scnt, NPOS);
        // XLA rewrites x / const -> x * (1/const). fl32(1/0.33f):
        const float recip033 = 3.03030300140380859375f;
        float nnf = __fmul_rn((float)P, recip033);
        int needed = (int)nnf - P;                  // trunc toward zero (astype int32)
        needed = min(max(needed, 0), NNEG);
        for (int t = tid; t < NNEG; t += 512) {
            ull key = sk[t];
            bool valid = ((uint32_t)(key >> 32) > 0x80000000u) && (t < needed);
            int  idx   = (int)(0xFFFFFFFFu - (uint32_t)key);
            float4 p = make_float4(0.f, 0.f, 0.f, 0.f);
            if (valid) p = *reinterpret_cast<const float4*>(prop + (size_t)(b*NPROP + idx)*4);
            int slot = NPOS + t;
            float* rr = out + ROIS_OFF + (size_t)(b*NROI + slot)*4;
            rr[0] = p.x; rr[1] = p.y; rr[2] = p.z; rr[3] = p.w;
            out[CLS_OFF + b*NROI + slot] = 0.f;
            float* d = out + DEL_OFF + (size_t)(b*NROI + slot)*4;
            d[0] = 0.f; d[1] = 0.f; d[2] = 0.f; d[3] = 0.f;
        }
    }
}

// ---------------- Kernel 2: mask crop_and_resize ----------------
__global__ void k_mask(const float* __restrict__ masks, float* __restrict__ out) {
    int b = blockIdx.y, slot = blockIdx.x;
    float* o = out + MSK_OFF + (size_t)(b*NROI + slot)*(MH*MW);
    int g = -1;
    float y1 = 0.f, x1 = 0.f, y2 = 0.f, x2 = 0.f;
    if (slot < NPOS) {
        g  = g_posgt[b*NPOS + slot];
        y1 = g_posbox[(b*NPOS + slot)*4 + 0];
        x1 = g_posbox[(b*NPOS + slot)*4 + 1];
        y2 = g_posbox[(b*NPOS + slot)*4 + 2];
        x2 = g_posbox[(b*NPOS + slot)*4 + 3];
    }
    if (g < 0) {
        for (int p = threadIdx.x; p < MH*MW; p += blockDim.x) o[p] = 0.f;
        return;
    }
    const float* img = masks + (size_t)b*HH*WW*NGT + g;
    #pragma unroll 4
    for (int p = threadIdx.x; p < MH*MW; p += blockDim.x) {
        int i = p / MW, j = p % MW;
        float ty = __fdiv_rn((float)i, (float)(MH - 1));
        float tx = __fdiv_rn((float)j, (float)(MW - 1));
        float ys = (y1 + ty * (y2 - y1)) * (float)(HH - 1);
        float xs = (x1 + tx * (x2 - x1)) * (float)(WW - 1);
        float y0f = floorf(ys), x0f = floorf(xs);
        float fy = ys - y0f,    fx = xs - x0f;
        int y0  = min(max((int)y0f, 0), HH - 1);
        int y1i = min(y0 + 1, HH - 1);
        int x0  = min(max((int)x0f, 0), WW - 1);
        int x1i = min(x0 + 1, WW - 1);
        float m00 = __ldg(img + ((size_t)y0 *WW + x0 )*NGT);
        float m01 = __ldg(img + ((size_t)y0 *WW + x1i)*NGT);
        float m10 = __ldg(img + ((size_t)y1i*WW + x0 )*NGT);
        float m11 = __ldg(img + ((size_t)y1i*WW + x1i)*NGT);
        float v = m00*(1.f-fy)*(1.f-fx) + m01*(1.f-fy)*fx
                + m10*fy*(1.f-fx)       + m11*fy*fx;
        o[p] = rintf(v);   // jnp.round = round half to even
    }
}

// ---------------- launch ----------------
extern "C" void kernel_launch(void* const* d_in, const int* in_sizes, int n_in,
                              void* d_out, int out_size) {
    (void)in_sizes; (void)n_in; (void)out_size;
    const float* prop   = (const float*)d_in[0];
    const int*   cls    = (const int*)  d_in[1];
    const float* gbox   = (const float*)d_in[2];
    const float* masks  = (const float*)d_in[3];
    const float* stddev = (const float*)d_in[4];
    float* out = (float*)d_out;

    k_iou   <<<dim3(63, NB),   256>>>(prop, cls, gbox);   // 32 proposals/block, 8 lanes each
    k_sample<<<dim3(NB, 2),    512>>>(prop, cls, gbox, stddev, out);
    k_mask  <<<dim3(NROI, NB), 256>>>(masks, out);
}

// round 17
// speedup vs baseline: 1.0941x; 1.0941x over previous
#include <cuda_runtime.h>
#include <stdint.h>

// ---------------- problem constants ----------------
#define NB     16
#define NPROP  2000
#define NGT    100
#define NPOS   66
#define NNEG   134
#define NROI   200
#define HH     160
#define WW     160
#define MH     28
#define MW     28

// output layout (float32, concatenated flattened tuple)
#define ROIS_OFF 0
#define CLS_OFF  (NB*NROI*4)                 // 12800
#define DEL_OFF  (CLS_OFF + NB*NROI)         // 16000
#define MSK_OFF  (DEL_OFF + NB*NROI*4)       // 28800

// ---------------- scratch (__device__ globals; no allocs allowed) ----------------
__device__ unsigned char g_flags [NB*NPROP];  // bit0: iou_max>=0.5, bit1: proposal valid
__device__ float         g_posbox[NB*NPOS*4];
__device__ int           g_posgt [NB*NPOS];   // >=0: valid (pending argmax), -1: invalid

// ---------------- JAX threefry2x32 (partitionable-default semantics) ----------------
__device__ __forceinline__ void tf2x32(uint32_t k0, uint32_t k1,
                                       uint32_t x0, uint32_t x1,
                                       uint32_t &o0, uint32_t &o1) {
    uint32_t ks2 = k0 ^ k1 ^ 0x1BD11BDAu;
    x0 += k0; x1 += k1;
#define TF_RND(r) { x0 += x1; x1 = __funnelshift_l(x1, x1, (r)); x1 ^= x0; }
    TF_RND(13) TF_RND(15) TF_RND(26) TF_RND(6)
    x0 += k1;  x1 += ks2 + 1u;
    TF_RND(17) TF_RND(29) TF_RND(16) TF_RND(24)
    x0 += ks2; x1 += k0 + 2u;
    TF_RND(13) TF_RND(15) TF_RND(26) TF_RND(6)
    x0 += k0;  x1 += k1 + 3u;
    TF_RND(17) TF_RND(29) TF_RND(16) TF_RND(24)
    x0 += k1;  x1 += ks2 + 4u;
    TF_RND(13) TF_RND(15) TF_RND(26) TF_RND(6)
    x0 += ks2; x1 += k0 + 5u;
#undef TF_RND
    o0 = x0; o1 = x1;
}

__device__ __forceinline__ float jax_uniform(uint32_t k0, uint32_t k1, uint32_t i) {
    uint32_t a, b;
    tf2x32(k0, k1, 0u, i, a, b);
    uint32_t bits = a ^ b;
    return __uint_as_float((bits >> 9) | 0x3f800000u) - 1.0f;
}

__device__ __forceinline__ uint32_t fmap(float f) {
    uint32_t u = __float_as_uint(f);
    return (u >> 31) ? ~u : (u | 0x80000000u);
}

// ---------------- Kernel 0: per-proposal "max IoU >= 0.5" flag ----------------
// 4 lanes per proposal, 25 GTs each. No divisions: RN(inter/uni) >= 0.5
//   <=> inter >= 0.5*uni (exact, power-of-two multiply), except a ~2^-25
// relative band below 0.5*uni where RN may still round up to 0.5 — caught by
// a band test and resolved with exact divisions (essentially never taken).
__global__ __launch_bounds__(256) void k_iou(const float* __restrict__ prop,
                                             const int*   __restrict__ gcls,
                                             const float* __restrict__ gbox) {
    __shared__ float4 sg4[NGT];
    __shared__ float  sa [NGT];   // gt area, NaN if class invalid
    int b = blockIdx.y, tid = threadIdx.x;
    for (int t = tid; t < NGT; t += 256) {
        float4 g = *reinterpret_cast<const float4*>(gbox + (size_t)(b*NGT + t)*4);
        sg4[t] = g;
        float a2 = (g.z - g.x) * (g.w - g.y);
        sa[t] = (gcls[b*NGT + t] > 0) ? a2 : __int_as_float(0x7FC00000);
    }
    __syncthreads();

    int gi = blockIdx.x * 64 + (tid >> 2);   // proposal index within image
    int r  = tid & 3;                        // gt-quarter
    if (gi >= NPROP) return;

    const float4 p = *reinterpret_cast<const float4*>(prop + (size_t)(b*NPROP + gi)*4);
    float a1 = (p.z - p.x) * (p.w - p.y);

    bool flag = false, band = false;
    #pragma unroll
    for (int k = 0; k < 25; k++) {
        int g = r * 25 + k;
        float4 gb = sg4[g];
        float a2 = sa[g];
        float yA = fmaxf(p.x, gb.x), xA = fmaxf(p.y, gb.y);
        float yB = fminf(p.z, gb.z), xB = fminf(p.w, gb.w);
        float inter = fmaxf(yB - yA, 0.f) * fmaxf(xB - xA, 0.f);
        float uni = fmaxf(a1 + a2 - inter, 1e-10f);   // NaN a2 -> 1e-10, gated by gok
        bool gok = (a2 == a2);
        float h = __fmul_rn(0.5f, uni);               // exact
        bool d  = (inter >= h);
        flag |= gok && d;
        band |= gok && !d && (inter >= __fmul_rn(h, 0.99999988f));
    }
    unsigned fb = (flag ? 1u : 0u) | (band ? 2u : 0u);
    fb |= __shfl_xor_sync(0xFFFFFFFFu, fb, 1, 4);
    fb |= __shfl_xor_sync(0xFFFFFFFFu, fb, 2, 4);

    if (r == 0) {
        bool pos = (fb & 1u) != 0;
        if ((fb & 2u) && !pos) {                      // rare: exact recheck, all 100
            for (int g = 0; g < NGT; g++) {
                float a2 = sa[g];
                if (a2 != a2) continue;
                float4 gb = sg4[g];
                float yA = fmaxf(p.x, gb.x), xA = fmaxf(p.y, gb.y);
                float yB = fminf(p.z, gb.z), xB = fminf(p.w, gb.w);
                float inter = fmaxf(yB - yA, 0.f) * fmaxf(xB - xA, 0.f);
                float uni = fmaxf(a1 + a2 - inter, 1e-10f);
                if (__fdiv_rn(inter, uni) >= 0.5f) { pos = true; break; }
            }
        }
        bool valid = (p.x != 0.f) || (p.y != 0.f) || (p.z != 0.f) || (p.w != 0.f);
        g_flags[b*NPROP + gi] = (unsigned char)((pos ? 1 : 0) | (valid ? 2 : 0));
    }
}

// ---------------- helpers for register bitonic ----------------
typedef unsigned long long ull;
__device__ __forceinline__ void cmpex(ull &A, ull &B, bool desc) {
    if ((A < B) == desc) { ull t = A; A = B; B = t; }
}

// ---------------- Kernel 1: sampling. grid = (image, role[pos|neg]) ----------------
// Bitonic sort of 2048 64-bit keys, DESCENDING: key = (fmap(score)<<32) |
// (0xFFFFFFFF - idx) => descending score, ascending-index ties (lax.top_k).
__global__ __launch_bounds__(512) void k_sample(const float* __restrict__ prop,
                                                float*       __restrict__ out) {
    __shared__ ull sk[2048];
    __shared__ int scnt;
    int b = blockIdx.x, role = blockIdx.y, tid = threadIdx.x;

    uint32_t kb0, kb1, kp0, kp1, kn0, kn1;
    tf2x32(0u, 42u, 0u, (uint32_t)b, kb0, kb1);
    tf2x32(kb0, kb1, 0u, 0u, kp0, kp1);
    tf2x32(kb0, kb1, 0u, 1u, kn0, kn1);
    uint32_t sk0 = role ? kn0 : kp0, sk1 = role ? kn1 : kp1;

    if (tid == 0) scnt = 0;
    __syncthreads();

    ull reg[4];
    int cnt = 0;
    #pragma unroll
    for (int s = 0; s < 4; s++) {
        int i = tid * 4 + s;
        uint32_t key32 = 0;                       // filler sorts last
        if (i < NPROP) {
            unsigned char f = g_flags[b*NPROP + i];
            bool posc = (f & 3) == 3;             // iou>=0.5 && valid
            bool cand = role ? ((f & 2) && !(f & 1)) : posc;
            float sc = cand ? jax_uniform(sk0, sk1, (uint32_t)i) : -1.0f;
            key32 = fmap(sc);
            if (role && posc && jax_uniform(kp0, kp1, (uint32_t)i) > 0.0f) cnt++;
        }
        reg[s] = ((ull)key32 << 32) | (uint32_t)(0xFFFFFFFFu - (uint32_t)i);
    }
    if (role && cnt) atomicAdd(&scnt, cnt);

    for (int k = 2; k <= 2048; k <<= 1) {
        for (int j = k >> 1; j > 0; j >>= 1) {
            if (j >= 128) {
                __syncthreads();
                #pragma unroll
                for (int s = 0; s < 4; s++) sk[tid*4 + s] = reg[s];
                __syncthreads();
                #pragma unroll
                for (int s = 0; s < 4; s++) {
                    int e = tid*4 + s;
                    ull part = sk[e ^ j];
                    bool desc = ((e & k) == 0), lower = ((e & j) == 0);
                    bool takeMax = (desc == lower);
                    ull A = reg[s];
                    reg[s] = takeMax ? (A > part ? A : part) : (A < part ? A : part);
                }
            } else if (j >= 4) {
                int lx = j >> 2;
                bool lower = ((tid & lx) == 0);
                #pragma unroll
                for (int s = 0; s < 4; s++) {
                    ull part = __shfl_xor_sync(0xFFFFFFFFu, reg[s], lx);
                    int e = tid*4 + s;
                    bool desc = ((e & k) == 0);
                    bool takeMax = (desc == lower);
                    ull A = reg[s];
                    reg[s] = takeMax ? (A > part ? A : part) : (A < part ? A : part);
                }
            } else if (j == 2) {
                bool desc = (((tid*4) & k) == 0);
                cmpex(reg[0], reg[2], desc);
                cmpex(reg[1], reg[3], desc);
            } else {
                if (k == 2) { cmpex(reg[0], reg[1], true); cmpex(reg[2], reg[3], false); }
                else {
                    bool desc = (((tid*4) & k) == 0);
                    cmpex(reg[0], reg[1], desc);
                    cmpex(reg[2], reg[3], desc);
                }
            }
        }
    }
    __syncthreads();
    #pragma unroll
    for (int s = 0; s < 4; s++) sk[tid*4 + s] = reg[s];
    __syncthreads();

    if (role == 0) {
        // ---- positives: slots [0,66): rois + metadata (cls/deltas in k_mask) ----
        if (tid < NPOS) {
            int t = tid;
            ull key = sk[t];
            bool valid = (uint32_t)(key >> 32) > 0x80000000u;   // score > 0
            int  idx   = (int)(0xFFFFFFFFu - (uint32_t)key);
            const float4 p = *reinterpret_cast<const float4*>(prop + (size_t)(b*NPROP + idx)*4);

            float* rr = out + ROIS_OFF + (size_t)(b*NROI + t)*4;
            rr[0] = valid ? p.x : 0.f; rr[1] = valid ? p.y : 0.f;
            rr[2] = valid ? p.z : 0.f; rr[3] = valid ? p.w : 0.f;

            g_posbox[(b*NPOS + t)*4 + 0] = p.x;
            g_posbox[(b*NPOS + t)*4 + 1] = p.y;
            g_posbox[(b*NPOS + t)*4 + 2] = p.z;
            g_posbox[(b*NPOS + t)*4 + 3] = p.w;
            g_posgt[b*NPOS + t] = valid ? 0 : -1;
        }
    } else {
        // ---- negatives: slots [66,200) ----
        int P = min(scnt, NPOS);
        // XLA rewrites x / const -> x * (1/const). fl32(1/0.33f):
        const float recip033 = 3.03030300140380859375f;
        float nnf = __fmul_rn((float)P, recip033);
        int needed = (int)nnf - P;                  // trunc toward zero (astype int32)
        needed = min(max(needed, 0), NNEG);
        for (int t = tid; t < NNEG; t += 512) {
            ull key = sk[t];
            bool valid = ((uint32_t)(key >> 32) > 0x80000000u) && (t < needed);
            int  idx   = (int)(0xFFFFFFFFu - (uint32_t)key);
            float4 p = make_float4(0.f, 0.f, 0.f, 0.f);
            if (valid) p = *reinterpret_cast<const float4*>(prop + (size_t)(b*NPROP + idx)*4);
            int slot = NPOS + t;
            float* rr = out + ROIS_OFF + (size_t)(b*NROI + slot)*4;
            rr[0] = p.x; rr[1] = p.y; rr[2] = p.z; rr[3] = p.w;
            out[CLS_OFF + b*NROI + slot] = 0.f;
            float* d = out + DEL_OFF + (size_t)(b*NROI + slot)*4;
            d[0] = 0.f; d[1] = 0.f; d[2] = 0.f; d[3] = 0.f;
        }
    }
}

// ---------------- Kernel 2: argmax + class/deltas + mask crop_and_resize ----------------
__global__ __launch_bounds__(256) void k_mask(const float* __restrict__ masks,
                                              const int*   __restrict__ gcls,
                                              const float* __restrict__ gbox,
                                              const float* __restrict__ stddev,
                                              float*       __restrict__ out) {
    int b = blockIdx.y, slot = blockIdx.x, tid = threadIdx.x;
    float* o = out + MSK_OFF + (size_t)(b*NROI + slot)*(MH*MW);

    if (slot >= NPOS) {       // negative slots: zero masks only
        for (int p = tid; p < MH*MW; p += 256) o[p] = 0.f;
        return;
    }

    bool valid = g_posgt[b*NPOS + slot] >= 0;
    const float4 pb = *reinterpret_cast<const float4*>(&g_posbox[(size_t)(b*NPOS + slot)*4]);

    if (!valid) {
        if (tid == 0) {
            out[CLS_OFF + b*NROI + slot] = 0.f;
            float* d = out + DEL_OFF + (size_t)(b*NROI + slot)*4;
            d[0] = 0.f; d[1] = 0.f; d[2] = 0.f; d[3] = 0.f;
        }
        for (int p = tid; p < MH*MW; p += 256) o[p] = 0.f;
        return;
    }

    // ---- exact argmax over 100 GTs (overlaps row: -1 where gt invalid) ----
    __shared__ ull red[128];
    float a1 = (pb.z - pb.x) * (pb.w - pb.y);
    if (tid < 128) {
        uint32_t key32 = 0;                       // padding sorts last
        if (tid < NGT) {
            float4 gb = *reinterpret_cast<const float4*>(gbox + (size_t)(b*NGT + tid)*4);
            bool gok = gcls[b*NGT + tid] > 0;
            float yA = fmaxf(pb.x, gb.x), xA = fmaxf(pb.y, gb.y);
            float yB = fminf(pb.z, gb.z), xB = fminf(pb.w, gb.w);
            float inter = fmaxf(yB - yA, 0.f) * fmaxf(xB - xA, 0.f);
            float a2 = (gb.z - gb.x) * (gb.w - gb.y);
            float uni = fmaxf(a1 + a2 - inter, 1e-10f);
            float q = gok ? __fdiv_rn(inter, uni) : -1.0f;
            key32 = fmap(q);
        }
        red[tid] = ((ull)key32 << 32) | (uint32_t)(0xFFFFFFFFu - (uint32_t)tid);
    }
    __syncthreads();
    #pragma unroll
    for (int s = 64; s > 0; s >>= 1) {
        if (tid < s) { ull a = red[tid], c = red[tid + s]; if (c > a) red[tid] = c; }
        __syncthreads();
    }
    int g = (int)(0xFFFFFFFFu - (uint32_t)red[0]);

    if (tid == 0) {
        float4 gb = *reinterpret_cast<const float4*>(gbox + (size_t)(b*NGT + g)*4);
        out[CLS_OFF + b*NROI + slot] = (float)gcls[b*NGT + g];
        float h  = pb.z - pb.x,  w  = pb.w - pb.y;
        float cy = pb.x + 0.5f*h, cx = pb.y + 0.5f*w;
        float gh = gb.z - gb.x, gw = gb.w - gb.y;
        float gcy = gb.x + 0.5f*gh, gcx = gb.y + 0.5f*gw;
        float* d = out + DEL_OFF + (size_t)(b*NROI + slot)*4;
        d[0] = __fdiv_rn(__fdiv_rn(gcy - cy, h), stddev[0]);
        d[1] = __fdiv_rn(__fdiv_rn(gcx - cx, w), stddev[1]);
        d[2] = __fdiv_rn(logf(__fdiv_rn(gh, h)), stddev[2]);
        d[3] = __fdiv_rn(logf(__fdiv_rn(gw, w)), stddev[3]);
    }

    // ---- bilinear crop_and_resize ----
    const float* img = masks + (size_t)b*HH*WW*NGT + g;
    #pragma unroll 4
    for (int p = tid; p < MH*MW; p += 256) {
        int i = p / MW, j = p % MW;
        float ty = __fdiv_rn((float)i, (float)(MH - 1));
        float tx = __fdiv_rn((float)j, (float)(MW - 1));
        float ys = (pb.x + ty * (pb.z - pb.x)) * (float)(HH - 1);
        float xs = (pb.y + tx * (pb.w - pb.y)) * (float)(WW - 1);
        float y0f = floorf(ys), x0f = floorf(xs);
        float fy = ys - y0f,    fx = xs - x0f;
        int y0  = min(max((int)y0f, 0), HH - 1);
        int y1i = min(y0 + 1, HH - 1);
        int x0  = min(max((int)x0f, 0), WW - 1);
        int x1i = min(x0 + 1, WW - 1);
        float m00 = __ldg(img + ((size_t)y0 *WW + x0 )*NGT);
        float m01 = __ldg(img + ((size_t)y0 *WW + x1i)*NGT);
        float m10 = __ldg(img + ((size_t)y1i*WW + x0 )*NGT);
        float m11 = __ldg(img + ((size_t)y1i*WW + x1i)*NGT);
        float v = m00*(1.f-fy)*(1.f-fx) + m01*(1.f-fy)*fx
                + m10*fy*(1.f-fx)       + m11*fy*fx;
        o[p] = rintf(v);   // jnp.round = round half to even
    }
}

// ---------------- launch ----------------
extern "C" void kernel_launch(void* const* d_in, const int* in_sizes, int n_in,
                              void* d_out, int out_size) {
    (void)in_sizes; (void)n_in; (void)out_size;
    const float* prop   = (const float*)d_in[0];
    const int*   cls    = (const int*)  d_in[1];
    const float* gbox   = (const float*)d_in[2];
    const float* masks  = (const float*)d_in[3];
    const float* stddev = (const float*)d_in[4];
    float* out = (float*)d_out;

    k_iou   <<<dim3(32, NB),   256>>>(prop, cls, gbox);   // 64 proposals/block, 4 lanes each
    k_sample<<<dim3(NB, 2),    512>>>(prop, out);
    k_mask  <<<dim3(NROI, NB), 256>>>(masks, cls, gbox, stddev, out);
}